// round 1
// baseline (speedup 1.0000x reference)
#include <cuda_runtime.h>
#include <math.h>

#define ACT_NONE 0
#define ACT_TANH 1
#define ACT_RELU 2

// ---- scratch layout (floats) in one __device__ buffer (zero-initialized) ----
#define O_POOL1 0
#define O_POOL2 65536
#define O_TA    131072
#define O_TB    196608
#define O_O0    262144
#define O_BVIS  327680
#define O_BAUD  393216
#define O_SA    458752
#define O_SB    589824
#define O_H1    720896
#define O_OT    851968
#define O_PART  917504
#define O_CNT   1966080
#define BUF_TOTAL 1966208

__device__ float g_buf[BUF_TOTAL];

// ============================================================================
// Pooling: pooled = mean over token axis.  X1 (64,196,1024), X2 (64,400,1024)
// grid (64, 8): y<4 -> X1 dim-chunk y, y>=4 -> X2 dim-chunk y-4
// ============================================================================
__global__ void __launch_bounds__(256) pool_kernel(
    const float* __restrict__ X1, const float* __restrict__ X2,
    float* __restrict__ p1, float* __restrict__ p2)
{
    int b = blockIdx.x;
    int y = blockIdx.y;
    int d = (y & 3) * 256 + threadIdx.x;
    if (y < 4) {
        const float* p = X1 + ((size_t)b * 196) * 1024 + d;
        float a = 0.f;
        #pragma unroll 4
        for (int n = 0; n < 196; n++) a += p[(size_t)n * 1024];
        p1[b * 1024 + d] = a * (1.0f / 196.0f);
    } else {
        const float* p = X2 + ((size_t)b * 400) * 1024 + d;
        float a = 0.f;
        #pragma unroll 4
        for (int n = 0; n < 400; n++) a += p[(size_t)n * 1024];
        p2[b * 1024 + d] = a * (1.0f / 400.0f);
    }
}

// ============================================================================
// o0 = 0.5 * (tanh(...)_A + tanh(...)_B)   (tanh already applied in GEMM)
// ============================================================================
__global__ void __launch_bounds__(256) combine_kernel(
    const float* __restrict__ a, const float* __restrict__ b, float* __restrict__ o)
{
    int i = blockIdx.x * 256 + threadIdx.x;
    o[i] = 0.5f * (a[i] + b[i]);
}

// ============================================================================
// Generic fp32 GEMM for M=64:  C = act( [A0|A1] @ [W0;W1] + bias )
//  - A pieces row-major (64, K0) and (64, K1); W pieces row-major with ldw = N.
//  - Split-K across gridDim.y; partials to `partial` (pld = gridDim.x*64).
//  - Last split-block per column tile (atomic counter) sums partials in fixed
//    order (deterministic) and writes the activated output.
//  - out == nullptr (counters == nullptr): leave raw partials for a consumer.
// Tile: BM=64, BN=64, BK=16, 256 threads, 4x4 outputs/thread.
// ============================================================================
__global__ void __launch_bounds__(256) gemm64_kernel(
    const float* __restrict__ A0, int K0,
    const float* __restrict__ A1, int K1,
    const float* __restrict__ W0, const float* __restrict__ W1, int ldw,
    const float* __restrict__ bias,
    float* __restrict__ partial, int pld,
    float* __restrict__ out, int ldo,
    int N, int act, int Kchunk, int SK, int* __restrict__ counters)
{
    const int BN = 64, BK = 16;
    __shared__ float sA[BK][64];
    __shared__ float sW[BK][BN];

    int tid = threadIdx.x;
    int colblk = blockIdx.x, split = blockIdx.y;
    int n0 = colblk * BN;
    bool edge = (n0 + BN > N);

    int tx = tid & 15;        // row group (4 rows)
    int ty = tid >> 4;        // col group (4 cols)
    int am = tid >> 2;        // A load: row 0..63
    int ak = (tid & 3) * 4;   // A load: k offset 0,4,8,12
    int wk = tid >> 4;        // W load: k 0..15
    int wn = (tid & 15) * 4;  // W load: n offset 0..60

    float acc[4][4];
    #pragma unroll
    for (int i = 0; i < 4; i++)
        #pragma unroll
        for (int j = 0; j < 4; j++) acc[i][j] = 0.f;

    int kbeg = split * Kchunk;
    for (int ks = kbeg; ks < kbeg + Kchunk; ks += BK) {
        // ---- stage A tile (64 x 16), k-major in smem ----
        bool p0 = (ks < K0);   // piece boundaries are multiples of BK
        const float* Ap = p0 ? A0 : A1;
        int Kp         = p0 ? K0 : K1;
        int klA        = (p0 ? ks : ks - K0) + ak;
        float4 a4 = *(const float4*)(Ap + (size_t)am * Kp + klA);
        sA[ak + 0][am] = a4.x; sA[ak + 1][am] = a4.y;
        sA[ak + 2][am] = a4.z; sA[ak + 3][am] = a4.w;

        // ---- stage W tile (16 x 64) ----
        const float* Wp = p0 ? W0 : W1;
        int klW = (p0 ? ks : ks - K0) + wk;
        if (!edge) {
            float4 w4 = *(const float4*)(Wp + (size_t)klW * ldw + n0 + wn);
            *(float4*)&sW[wk][wn] = w4;
        } else {
            #pragma unroll
            for (int j = 0; j < 4; j++) {
                int n = n0 + wn + j;
                sW[wk][wn + j] = (n < N) ? Wp[(size_t)klW * ldw + n] : 0.f;
            }
        }
        __syncthreads();

        #pragma unroll
        for (int k = 0; k < BK; k++) {
            float4 av = *(const float4*)&sA[k][tx * 4];
            float4 wv = *(const float4*)&sW[k][ty * 4];
            float a[4] = {av.x, av.y, av.z, av.w};
            float w[4] = {wv.x, wv.y, wv.z, wv.w};
            #pragma unroll
            for (int i = 0; i < 4; i++)
                #pragma unroll
                for (int j = 0; j < 4; j++)
                    acc[i][j] = fmaf(a[i], w[j], acc[i][j]);
        }
        __syncthreads();
    }

    if (SK == 1) {
        #pragma unroll
        for (int i = 0; i < 4; i++) {
            int m = tx * 4 + i;
            #pragma unroll
            for (int j = 0; j < 4; j++) {
                int n = n0 + ty * 4 + j;
                if (n < N) {
                    float v = acc[i][j] + (bias ? bias[n] : 0.f);
                    if (act == ACT_TANH) v = tanhf(v);
                    else if (act == ACT_RELU) v = fmaxf(v, 0.f);
                    out[(size_t)m * ldo + n] = v;
                }
            }
        }
        return;
    }

    // ---- write split-K partials (aligned float4) ----
    #pragma unroll
    for (int i = 0; i < 4; i++) {
        int m = tx * 4 + i;
        size_t idx = ((size_t)(split * 64 + m)) * pld + n0 + ty * 4;
        *(float4*)&partial[idx] = make_float4(acc[i][0], acc[i][1], acc[i][2], acc[i][3]);
    }
    if (counters == nullptr) return;   // consumer will read raw partials

    __threadfence();
    __syncthreads();
    __shared__ int sLast;
    if (tid == 0) {
        int old = atomicAdd(&counters[colblk], 1);
        sLast = (old == SK - 1);
    }
    __syncthreads();
    if (!sLast) return;

    // last block for this column tile: reduce in fixed order + epilogue
    #pragma unroll
    for (int i = 0; i < 4; i++) {
        int m = tx * 4 + i;
        #pragma unroll
        for (int j = 0; j < 4; j++) {
            int n = n0 + ty * 4 + j;
            if (n >= N) continue;
            float v = bias ? bias[n] : 0.f;
            for (int s = 0; s < SK; s++)
                v += partial[((size_t)(s * 64 + m)) * pld + n];
            if (act == ACT_TANH) v = tanhf(v);
            else if (act == ACT_RELU) v = fmaxf(v, 0.f);
            out[(size_t)m * ldo + n] = v;
        }
    }
    if (tid == 0) counters[colblk] = 0;   // self-reset for next GEMM launch
}

// ============================================================================
// Policy head: from raw h2 partials (SK=8, pld=2048) compute per sample:
//   h2 = relu(sum partials + b_h2); logits = h2@W_M+b_M; l = tanh(h2@W_L+b_L)
//   o_t = modality-routed tanh(base + rank-1/2 l-update).  One block per sample.
// ============================================================================
__global__ void __launch_bounds__(256) policy_kernel(
    const float* __restrict__ part, int sk,
    const float* __restrict__ b_h2,
    const float* __restrict__ W_M, const float* __restrict__ b_M,
    const float* __restrict__ W_L, const float* __restrict__ b_L,
    const float* __restrict__ W_loc1, const float* __restrict__ W_loc2,
    const float* __restrict__ bvis, const float* __restrict__ baud,
    float* __restrict__ ot)
{
    int b = blockIdx.x, tid = threadIdx.x;
    float m0 = 0.f, m1 = 0.f, l0 = 0.f, l1 = 0.f;
    for (int k = tid; k < 2048; k += 256) {
        float v = b_h2[k];
        #pragma unroll
        for (int s = 0; s < 8; s++)
            v += part[((size_t)(s * 64 + b)) * 2048 + k];
        v = fmaxf(v, 0.f);
        m0 += v * W_M[2 * k];     m1 += v * W_M[2 * k + 1];
        l0 += v * W_L[2 * k];     l1 += v * W_L[2 * k + 1];
    }
    __shared__ float red[4][256];
    red[0][tid] = m0; red[1][tid] = m1; red[2][tid] = l0; red[3][tid] = l1;
    __syncthreads();
    for (int off = 128; off > 0; off >>= 1) {
        if (tid < off)
            #pragma unroll
            for (int c = 0; c < 4; c++) red[c][tid] += red[c][tid + off];
        __syncthreads();
    }
    __shared__ int s_m; __shared__ float s_l0, s_l1;
    if (tid == 0) {
        float q0 = red[0][0] + b_M[0], q1 = red[1][0] + b_M[1];
        s_m  = (q1 > q0) ? 1 : 0;                 // argmax, first-index tie-break
        s_l0 = tanhf(red[2][0] + b_L[0]);
        s_l1 = tanhf(red[3][0] + b_L[1]);
    }
    __syncthreads();
    int m = s_m; float L0 = s_l0, L1 = s_l1;
    const float* wl1a = W_loc1 + (size_t)1024 * 1024;  // row 1024 (l0)
    const float* wl1b = W_loc1 + (size_t)1025 * 1024;  // row 1025 (l1)
    const float* wl2a = W_loc2 + (size_t)1024 * 1024;  // row 1024 (l0)
    for (int d = tid; d < 1024; d += 256) {
        float o;
        if (m == 0) o = tanhf(bvis[b * 1024 + d] + L0 * wl1a[d] + L1 * wl1b[d]);
        else        o = tanhf(baud[b * 1024 + d] + L0 * wl2a[d]);
        ot[b * 1024 + d] = o;
    }
}

// ============================================================================
// Host driver
// ============================================================================
static inline void launch_gemm(const float* A0, int K0, const float* A1, int K1,
                               const float* W0, const float* W1, int ldw,
                               const float* bias,
                               float* out, int ldo, int N, int act, int SK,
                               float* part, int* cnt)
{
    int cb = (N + 63) / 64;
    dim3 grid(cb, SK);
    gemm64_kernel<<<grid, 256>>>(A0, K0, A1, K1, W0, W1, ldw, bias,
                                 part, cb * 64, out, ldo, N, act,
                                 (K0 + K1) / SK, SK, out ? cnt : (int*)nullptr);
}

extern "C" void kernel_launch(void* const* d_in, const int* in_sizes, int n_in,
                              void* d_out, int out_size)
{
    const float* X1      = (const float*)d_in[0];
    const float* X2      = (const float*)d_in[1];
    const float* z       = (const float*)d_in[2];
    const float* W_pool1 = (const float*)d_in[3];
    const float* b_pool1 = (const float*)d_in[4];
    const float* W_loc1  = (const float*)d_in[5];
    const float* b_loc1  = (const float*)d_in[6];
    const float* W_pool2 = (const float*)d_in[7];
    const float* b_pool2 = (const float*)d_in[8];
    const float* W_loc2  = (const float*)d_in[9];
    const float* b_loc2  = (const float*)d_in[10];
    const float* W_ss    = (const float*)d_in[11];
    const float* W_os    = (const float*)d_in[12];
    const float* b_s     = (const float*)d_in[13];
    const float* W_h1    = (const float*)d_in[14];
    const float* b_h1    = (const float*)d_in[15];
    const float* W_h2    = (const float*)d_in[16];
    const float* b_h2    = (const float*)d_in[17];
    const float* W_M     = (const float*)d_in[18];
    const float* b_M     = (const float*)d_in[19];
    const float* W_L     = (const float*)d_in[20];
    const float* b_L     = (const float*)d_in[21];
    // d_in[22]=W_v, d_in[23]=b_v : unused in forward pass
    const float* W_q     = (const float*)d_in[24];
    const float* b_q     = (const float*)d_in[25];
    float* out = (float*)d_out;

    float* base = nullptr;
    cudaGetSymbolAddress((void**)&base, g_buf);
    float* pool1 = base + O_POOL1;
    float* pool2 = base + O_POOL2;
    float* tA    = base + O_TA;
    float* tB    = base + O_TB;
    float* o0    = base + O_O0;
    float* bvis  = base + O_BVIS;
    float* baud  = base + O_BAUD;
    float* sA    = base + O_SA;
    float* sB    = base + O_SB;
    float* h1    = base + O_H1;
    float* ot    = base + O_OT;
    float* part  = base + O_PART;
    int*   cnt   = (int*)(base + O_CNT);

    // ---- setup ----
    pool_kernel<<<dim3(64, 8), 256>>>(X1, X2, pool1, pool2);
    launch_gemm(pool1, 1024, nullptr, 0, W_pool1, nullptr, 1024, b_pool1,
                tA, 1024, 1024, ACT_TANH, 8, part, cnt);
    launch_gemm(pool2, 1024, nullptr, 0, W_pool2, nullptr, 1024, b_pool2,
                tB, 1024, 1024, ACT_TANH, 8, part, cnt);
    launch_gemm(pool1, 1024, nullptr, 0, W_loc1, nullptr, 1024, b_loc1,
                bvis, 1024, 1024, ACT_NONE, 8, part, cnt);
    launch_gemm(pool2, 1024, nullptr, 0, W_loc2, nullptr, 1024, b_loc2,
                baud, 1024, 1024, ACT_NONE, 8, part, cnt);
    combine_kernel<<<256, 256>>>(tA, tB, o0);
    // s1 = tanh(o0 @ W_os + b_s)   (s0 = 0 so the W_ss term vanishes)
    launch_gemm(o0, 1024, nullptr, 0, W_os, nullptr, 2048, b_s,
                sA, 2048, 2048, ACT_TANH, 4, part, cnt);

    float* scur = sA;
    float* snxt = sB;
    const float* Wh1_z = W_h1 + (size_t)2048 * 2048;  // rows for z piece
    const float* Wq_z  = W_q  + (size_t)2048 * 1000;

    // ---- T = 4 sequential steps ----
    for (int t = 0; t < 4; t++) {
        // h1 = relu([s, z] @ W_h1 + b_h1)
        launch_gemm(scur, 2048, z, 1024, W_h1, Wh1_z, 2048, b_h1,
                    h1, 2048, 2048, ACT_RELU, 8, part, cnt);
        // raw partials of h1 @ W_h2 (no finalize; policy kernel consumes them)
        launch_gemm(h1, 2048, nullptr, 0, W_h2, nullptr, 2048, b_h2,
                    nullptr, 0, 2048, ACT_NONE, 8, part, cnt);
        // argmax-modality + location policy + o_t routing
        policy_kernel<<<64, 256>>>(part, 8, b_h2, W_M, b_M, W_L, b_L,
                                   W_loc1, W_loc2, bvis, baud, ot);
        // s' = tanh(s @ W_ss + o_t @ W_os + b_s)
        launch_gemm(scur, 2048, ot, 1024, W_ss, W_os, 2048, b_s,
                    snxt, 2048, 2048, ACT_TANH, 8, part, cnt);
        // y_t = [s', z] @ W_q + b_q   -> out[:, t, :]
        launch_gemm(snxt, 2048, z, 1024, W_q, Wq_z, 1000, b_q,
                    out + t * 1000, 4000, 1000, ACT_NONE, 8, part, cnt);
        float* tmp = scur; scur = snxt; snxt = tmp;
    }
}

// round 15
// speedup vs baseline: 1.3647x; 1.3647x over previous
#include <cuda_runtime.h>
#include <cuda_bf16.h>
#include <math.h>

typedef __nv_bfloat16 bf16;

#define ACT_NONE 0
#define ACT_TANH 1
#define ACT_RELU 2

// ---------------- fp32 scratch ----------------
#define OF_P1   0
#define OF_P2   65536
#define OF_TA   131072
#define OF_TB   196608
#define OF_O0   262144
#define OF_BV   327680
#define OF_BA   393216
#define OF_CZ   458752
#define OF_CQ   589824
#define OF_S0   655360
#define OF_S1   786432
#define OF_H1   917504
#define OF_H2   1048576
#define OF_OT   1179648
#define OF_PART 1245184
#define OF_CNT  3342336
#define F_TOTAL 3342464
__device__ float g_f[F_TOTAL];

// ---------------- bf16 hi/lo weight scratch ----------------
#define OW_POOL1 0L
#define OW_POOL2 1048576L
#define OW_LOC1  2097152L
#define OW_LOC2  3145728L
#define OW_OS    4194304L
#define OW_SS    6291456L
#define OW_H1    10485760L
#define OW_H2    16777216L
#define OW_Q     20971520L
#define W_TOTAL  24043520L
__device__ bf16 g_h[W_TOTAL];
__device__ bf16 g_l[W_TOTAL];

// ---------------- small helpers ----------------
__device__ __forceinline__ unsigned smem_u32(const void* p) {
    return (unsigned)__cvta_generic_to_shared(p);
}
__device__ __forceinline__ void cp16(unsigned dst, const void* src) {
    asm volatile("cp.async.cg.shared.global [%0], [%1], 16;\n" :: "r"(dst), "l"(src));
}
__device__ __forceinline__ void cp_commit() { asm volatile("cp.async.commit_group;\n"); }
__device__ __forceinline__ void cp_wait0()  { asm volatile("cp.async.wait_group 0;\n"); }

__device__ __forceinline__ void ldsm4(unsigned r[4], unsigned addr) {
    asm volatile("ldmatrix.sync.aligned.m8n8.x4.shared.b16 {%0,%1,%2,%3},[%4];\n"
                 : "=r"(r[0]), "=r"(r[1]), "=r"(r[2]), "=r"(r[3]) : "r"(addr));
}
__device__ __forceinline__ void ldsm4t(unsigned r[4], unsigned addr) {
    asm volatile("ldmatrix.sync.aligned.m8n8.x4.trans.shared.b16 {%0,%1,%2,%3},[%4];\n"
                 : "=r"(r[0]), "=r"(r[1]), "=r"(r[2]), "=r"(r[3]) : "r"(addr));
}
__device__ __forceinline__ void mma_bf16(float c[4], const unsigned a[4], unsigned b0, unsigned b1) {
    asm volatile(
        "mma.sync.aligned.m16n8k16.row.col.f32.bf16.bf16.f32 "
        "{%0,%1,%2,%3},{%4,%5,%6,%7},{%8,%9},{%0,%1,%2,%3};\n"
        : "+f"(c[0]), "+f"(c[1]), "+f"(c[2]), "+f"(c[3])
        : "r"(a[0]), "r"(a[1]), "r"(a[2]), "r"(a[3]), "r"(b0), "r"(b1));
}
__device__ __forceinline__ unsigned pk(bf16 a, bf16 b) {
    unsigned short ua = *(unsigned short*)&a, ub = *(unsigned short*)&b;
    return (unsigned)ua | ((unsigned)ub << 16);
}

// ============================================================================
// Pooling: mean over token axis. X1 (64,196,1024), X2 (64,400,1024)
// ============================================================================
__global__ void __launch_bounds__(256) pool_kernel(
    const float* __restrict__ X1, const float* __restrict__ X2,
    float* __restrict__ p1, float* __restrict__ p2)
{
    int b = blockIdx.x, y = blockIdx.y;
    int d = (y & 3) * 256 + threadIdx.x;
    if (y < 4) {
        const float* p = X1 + ((size_t)b * 196) * 1024 + d;
        float a = 0.f;
        #pragma unroll 4
        for (int n = 0; n < 196; n++) a += p[(size_t)n * 1024];
        p1[b * 1024 + d] = a * (1.0f / 196.0f);
    } else {
        const float* p = X2 + ((size_t)b * 400) * 1024 + d;
        float a = 0.f;
        #pragma unroll 4
        for (int n = 0; n < 400; n++) a += p[(size_t)n * 1024];
        p2[b * 1024 + d] = a * (1.0f / 400.0f);
    }
}

// ============================================================================
// Weight conversion: fp32 -> (hi, lo) bf16 pairs.  9 segments in one launch.
// ============================================================================
struct Seg  { const float* s; long off; long n; };
struct Cvt9 { Seg g[9]; };

__global__ void __launch_bounds__(256) cvt_kernel(Cvt9 a, bf16* __restrict__ H, bf16* __restrict__ L)
{
    Seg sg = a.g[blockIdx.y];
    long stride = (long)gridDim.x * 256 * 4;
    for (long i = ((long)blockIdx.x * 256 + threadIdx.x) * 4; i < sg.n; i += stride) {
        float4 v = *(const float4*)(sg.s + i);
        bf16 h0 = __float2bfloat16(v.x), h1 = __float2bfloat16(v.y);
        bf16 h2 = __float2bfloat16(v.z), h3 = __float2bfloat16(v.w);
        bf16 l0 = __float2bfloat16(v.x - __bfloat162float(h0));
        bf16 l1 = __float2bfloat16(v.y - __bfloat162float(h1));
        bf16 l2 = __float2bfloat16(v.z - __bfloat162float(h2));
        bf16 l3 = __float2bfloat16(v.w - __bfloat162float(h3));
        uint2 uh = make_uint2(pk(h0, h1), pk(h2, h3));
        uint2 ul = make_uint2(pk(l0, l1), pk(l2, l3));
        *(uint2*)(H + sg.off + i) = uh;
        *(uint2*)(L + sg.off + i) = ul;
    }
}

// ============================================================================
// o0 = 0.5 * (tA + tB)
// ============================================================================
__global__ void __launch_bounds__(256) combine_kernel(
    const float* __restrict__ a, const float* __restrict__ b, float* __restrict__ o)
{
    int i = blockIdx.x * 256 + threadIdx.x;
    o[i] = 0.5f * (a[i] + b[i]);
}

// ============================================================================
// Split-bf16 tensor-core GEMM, M=64:
//   C = act( [A0|A1] @ [W0;W1] + bias + Dadd )
// computed as a_hi*w_hi + a_hi*w_lo + a_lo*w_hi with fp32 accumulation.
// A pieces fp32 row-major (split to hi/lo on the fly); W pieces pre-split
// bf16 hi/lo row-major (K x N, ldw = N).  Split-K over gridDim.y; the last
// block per column tile (atomic counter) reduces partials in fixed order.
// Tile: BM=64, BN=128, BK=32(fp32 K), 256 thr (8 warps, 2x4, warp tile 32x32).
// ============================================================================
__global__ void __launch_bounds__(256) mgemm(
    const float* __restrict__ A0, int K0,
    const float* __restrict__ A1, int K1,
    const bf16* __restrict__ Wh0, const bf16* __restrict__ Wl0,
    const bf16* __restrict__ Wh1, const bf16* __restrict__ Wl1, int ldw,
    const float* __restrict__ bias, const float* __restrict__ Dadd, int ldd,
    float* __restrict__ partial, int pld,
    float* __restrict__ out, int ldo,
    int N, int act, int Kchunk, int SK, int* __restrict__ counters)
{
    __shared__ __align__(16) bf16 sAh[64 * 40];
    __shared__ __align__(16) bf16 sAl[64 * 40];
    __shared__ __align__(16) bf16 sW[2][2][32 * 136];   // [buf][hi/lo]

    const int tid = threadIdx.x;
    const int lane = tid & 31, warp = tid >> 5;
    const int wm = warp >> 2, wn = warp & 3;
    const int colblk = blockIdx.x, split = blockIdx.y;
    const int n0 = colblk * 128;

    float acc[2][4][4];
    #pragma unroll
    for (int i = 0; i < 2; i++)
        #pragma unroll
        for (int j = 0; j < 4; j++)
            #pragma unroll
            for (int r = 0; r < 4; r++) acc[i][j][r] = 0.f;

    // loader indices
    const int ar = tid >> 2;            // A row 0..63
    const int ac = (tid & 3) * 8;       // A k-offset 0,8,16,24
    const int wr = tid >> 3;            // W k-row 0..31
    const int wc = (tid & 7) * 16;      // W n-offset 0..112
    const int wn_g = n0 + wc;
    const bool wv0 = (wn_g     < N);
    const bool wv1 = (wn_g + 8 < N);

    // fragment smem byte offsets
    const unsigned aBaseH = smem_u32(sAh);
    const unsigned aBaseL = smem_u32(sAl);
    const unsigned aoff0 = (unsigned)(((wm * 32 + (lane & 15)) * 40 + (lane >> 4) * 8) * 2);
    const unsigned aoff1 = aoff0 + 16 * 40 * 2;
    const unsigned woff0 = (unsigned)((((lane & 7) + ((lane >> 3) & 1) * 8) * 136
                                      + wn * 32 + (lane >> 4) * 8) * 2);
    const unsigned woff1 = woff0 + 32;

    const int kbeg = split * Kchunk;
    const int nchunks = Kchunk / 32;

    float areg[8];

    auto loadA = [&](int kg) {
        bool p0 = (kg < K0);
        const float* Ap = p0 ? A0 : A1;
        int Kp = p0 ? K0 : K1;
        const float4* s = (const float4*)(Ap + (size_t)ar * Kp + (p0 ? kg : kg - K0) + ac);
        float4 u = s[0], v = s[1];
        areg[0] = u.x; areg[1] = u.y; areg[2] = u.z; areg[3] = u.w;
        areg[4] = v.x; areg[5] = v.y; areg[6] = v.z; areg[7] = v.w;
    };
    auto storeA = [&]() {
        bf16 h[8], l[8];
        #pragma unroll
        for (int j = 0; j < 8; j++) {
            h[j] = __float2bfloat16(areg[j]);
            l[j] = __float2bfloat16(areg[j] - __bfloat162float(h[j]));
        }
        *(uint4*)&sAh[ar * 40 + ac] = make_uint4(pk(h[0], h[1]), pk(h[2], h[3]), pk(h[4], h[5]), pk(h[6], h[7]));
        *(uint4*)&sAl[ar * 40 + ac] = make_uint4(pk(l[0], l[1]), pk(l[2], l[3]), pk(l[4], l[5]), pk(l[6], l[7]));
    };
    auto loadW = [&](int buf, int kg) {
        bool p0 = (kg < K0);
        const bf16* WH = p0 ? Wh0 : Wh1;
        const bf16* WL = p0 ? Wl0 : Wl1;
        size_t roff = (size_t)((p0 ? kg : kg - K0) + wr) * ldw + wn_g;
        bf16* dH = &sW[buf][0][wr * 136 + wc];
        bf16* dL = &sW[buf][1][wr * 136 + wc];
        if (wv0) { cp16(smem_u32(dH), WH + roff); cp16(smem_u32(dL), WL + roff); }
        else     { *(uint4*)dH = make_uint4(0,0,0,0); *(uint4*)dL = make_uint4(0,0,0,0); }
        if (wv1) { cp16(smem_u32(dH + 8), WH + roff + 8); cp16(smem_u32(dL + 8), WL + roff + 8); }
        else     { *(uint4*)(dH + 8) = make_uint4(0,0,0,0); *(uint4*)(dL + 8) = make_uint4(0,0,0,0); }
    };
    auto compute = [&](int buf) {
        #pragma unroll
        for (int p = 0; p < 3; p++) {
            unsigned aB = (p == 2) ? aBaseL : aBaseH;
            unsigned wB = smem_u32(&sW[buf][(p == 1) ? 1 : 0][0]);
            #pragma unroll
            for (int kk = 0; kk < 2; kk++) {
                unsigned a0[4], a1[4], b0r[4], b1r[4];
                ldsm4 (a0,  aB + aoff0 + kk * 32);
                ldsm4 (a1,  aB + aoff1 + kk * 32);
                ldsm4t(b0r, wB + woff0 + kk * 4352);
                ldsm4t(b1r, wB + woff1 + kk * 4352);
                mma_bf16(acc[0][0], a0, b0r[0], b0r[1]);
                mma_bf16(acc[0][1], a0, b0r[2], b0r[3]);
                mma_bf16(acc[0][2], a0, b1r[0], b1r[1]);
                mma_bf16(acc[0][3], a0, b1r[2], b1r[3]);
                mma_bf16(acc[1][0], a1, b0r[0], b0r[1]);
                mma_bf16(acc[1][1], a1, b0r[2], b0r[3]);
                mma_bf16(acc[1][2], a1, b1r[0], b1r[1]);
                mma_bf16(acc[1][3], a1, b1r[2], b1r[3]);
            }
        }
    };

    // prologue
    loadW(0, kbeg); cp_commit();
    loadA(kbeg); storeA();
    cp_wait0(); __syncthreads();

    for (int ci = 0; ci < nchunks; ci++) {
        int buf = ci & 1;
        bool nx = (ci + 1 < nchunks);
        if (nx) { loadW(buf ^ 1, kbeg + (ci + 1) * 32); cp_commit(); loadA(kbeg + (ci + 1) * 32); }
        compute(buf);
        __syncthreads();
        if (nx) storeA();
        cp_wait0();
        __syncthreads();
    }

    // ---- write split-K partials ----
    const int r0 = wm * 32 + (lane >> 2);
    const int c0 = wn * 32 + (lane & 3) * 2;
    #pragma unroll
    for (int mt = 0; mt < 2; mt++)
        #pragma unroll
        for (int nt = 0; nt < 4; nt++)
            #pragma unroll
            for (int pr = 0; pr < 2; pr++) {
                int row = r0 + mt * 16 + pr * 8;
                int col = n0 + c0 + nt * 8;
                *(float2*)&partial[((size_t)(split * 64 + row)) * pld + col] =
                    make_float2(acc[mt][nt][pr * 2], acc[mt][nt][pr * 2 + 1]);
            }

    __threadfence();
    __syncthreads();
    __shared__ int sLast;
    if (tid == 0) {
        int old = atomicAdd(&counters[colblk], 1);
        sLast = (old == SK - 1);
    }
    __syncthreads();
    if (!sLast) return;

    #pragma unroll
    for (int mt = 0; mt < 2; mt++)
        #pragma unroll
        for (int nt = 0; nt < 4; nt++)
            #pragma unroll
            for (int pr = 0; pr < 2; pr++) {
                int row = r0 + mt * 16 + pr * 8;
                int col = n0 + c0 + nt * 8;
                if (col >= N) continue;
                float vx = 0.f, vy = 0.f;
                for (int sp = 0; sp < SK; sp++) {
                    float2 t = *(const float2*)&partial[((size_t)(sp * 64 + row)) * pld + col];
                    vx += t.x; vy += t.y;
                }
                if (bias) { vx += bias[col]; vy += bias[col + 1]; }
                if (Dadd) { vx += Dadd[(size_t)row * ldd + col]; vy += Dadd[(size_t)row * ldd + col + 1]; }
                if (act == ACT_TANH) { vx = tanhf(vx); vy = tanhf(vy); }
                else if (act == ACT_RELU) { vx = fmaxf(vx, 0.f); vy = fmaxf(vy, 0.f); }
                out[(size_t)row * ldo + col]     = vx;
                out[(size_t)row * ldo + col + 1] = vy;
            }
    if (tid == 0) counters[colblk] = 0;
}

// ============================================================================
// Policy head: reads full h2 (already relu'd).  One block per sample:
//   logits = h2@W_M+b_M -> argmax; l = tanh(h2@W_L+b_L);
//   o_t = routed tanh(base + rank-1/2 update from l).
// ============================================================================
__global__ void __launch_bounds__(256) policy_kernel(
    const float* __restrict__ h2,
    const float* __restrict__ W_M, const float* __restrict__ b_M,
    const float* __restrict__ W_L, const float* __restrict__ b_L,
    const float* __restrict__ W_loc1, const float* __restrict__ W_loc2,
    const float* __restrict__ bvis, const float* __restrict__ baud,
    float* __restrict__ ot)
{
    int b = blockIdx.x, tid = threadIdx.x;
    float m0 = 0.f, m1 = 0.f, l0 = 0.f, l1 = 0.f;
    for (int k = tid; k < 2048; k += 256) {
        float v = h2[b * 2048 + k];
        m0 += v * W_M[2 * k];  m1 += v * W_M[2 * k + 1];
        l0 += v * W_L[2 * k];  l1 += v * W_L[2 * k + 1];
    }
    __shared__ float red[4][256];
    red[0][tid] = m0; red[1][tid] = m1; red[2][tid] = l0; red[3][tid] = l1;
    __syncthreads();
    for (int off = 128; off > 0; off >>= 1) {
        if (tid < off)
            #pragma unroll
            for (int c = 0; c < 4; c++) red[c][tid] += red[c][tid + off];
        __syncthreads();
    }
    __shared__ int s_m; __shared__ float s_l0, s_l1;
    if (tid == 0) {
        float q0 = red[0][0] + b_M[0], q1 = red[1][0] + b_M[1];
        s_m  = (q1 > q0) ? 1 : 0;
        s_l0 = tanhf(red[2][0] + b_L[0]);
        s_l1 = tanhf(red[3][0] + b_L[1]);
    }
    __syncthreads();
    int m = s_m; float L0 = s_l0, L1 = s_l1;
    const float* wl1a = W_loc1 + (size_t)1024 * 1024;
    const float* wl1b = W_loc1 + (size_t)1025 * 1024;
    const float* wl2a = W_loc2 + (size_t)1024 * 1024;
    for (int d = tid; d < 1024; d += 256) {
        float o;
        if (m == 0) o = tanhf(bvis[b * 1024 + d] + L0 * wl1a[d] + L1 * wl1b[d]);
        else        o = tanhf(baud[b * 1024 + d] + L0 * wl2a[d]);
        ot[b * 1024 + d] = o;
    }
}

// ============================================================================
// Host driver
// ============================================================================
static inline void launch_mgemm(const float* A0, int K0, const float* A1, int K1,
                                const bf16* Wh0, const bf16* Wl0,
                                const bf16* Wh1, const bf16* Wl1, int ldw,
                                const float* bias, const float* Dadd, int ldd,
                                float* out, int ldo, int N, int act, int SK,
                                float* part, int* cnt)
{
    int cb = (N + 127) / 128;
    int Kchunk = (K0 + K1) / SK;
    dim3 grid(cb, SK);
    mgemm<<<grid, 256>>>(A0, K0, A1, K1, Wh0, Wl0, Wh1, Wl1, ldw, bias, Dadd, ldd,
                         part, cb * 128, out, ldo, N, act, Kchunk, SK, cnt);
}

extern "C" void kernel_launch(void* const* d_in, const int* in_sizes, int n_in,
                              void* d_out, int out_size)
{
    const float* X1      = (const float*)d_in[0];
    const float* X2      = (const float*)d_in[1];
    const float* z       = (const float*)d_in[2];
    const float* W_pool1 = (const float*)d_in[3];
    const float* b_pool1 = (const float*)d_in[4];
    const float* W_loc1  = (const float*)d_in[5];
    const float* b_loc1  = (const float*)d_in[6];
    const float* W_pool2 = (const float*)d_in[7];
    const float* b_pool2 = (const float*)d_in[8];
    const float* W_loc2  = (const float*)d_in[9];
    const float* b_loc2  = (const float*)d_in[10];
    const float* W_ss    = (const float*)d_in[11];
    const float* W_os    = (const float*)d_in[12];
    const float* b_s     = (const float*)d_in[13];
    const float* W_h1    = (const float*)d_in[14];
    const float* b_h1    = (const float*)d_in[15];
    const float* W_h2    = (const float*)d_in[16];
    const float* b_h2    = (const float*)d_in[17];
    const float* W_M     = (const float*)d_in[18];
    const float* b_M     = (const float*)d_in[19];
    const float* W_L     = (const float*)d_in[20];
    const float* b_L     = (const float*)d_in[21];
    const float* W_q     = (const float*)d_in[24];
    const float* b_q     = (const float*)d_in[25];
    float* out = (float*)d_out;

    float* fb = nullptr;  bf16* wh = nullptr;  bf16* wl = nullptr;
    cudaGetSymbolAddress((void**)&fb, g_f);
    cudaGetSymbolAddress((void**)&wh, g_h);
    cudaGetSymbolAddress((void**)&wl, g_l);

    float* p1   = fb + OF_P1;
    float* p2   = fb + OF_P2;
    float* tA   = fb + OF_TA;
    float* tB   = fb + OF_TB;
    float* o0   = fb + OF_O0;
    float* bvis = fb + OF_BV;
    float* baud = fb + OF_BA;
    float* cz   = fb + OF_CZ;
    float* cq   = fb + OF_CQ;
    float* sA   = fb + OF_S0;
    float* sB   = fb + OF_S1;
    float* h1   = fb + OF_H1;
    float* h2   = fb + OF_H2;
    float* ot   = fb + OF_OT;
    float* part = fb + OF_PART;
    int*   cnt  = (int*)(fb + OF_CNT);

    // ---- pooling + weight conversion ----
    pool_kernel<<<dim3(64, 8), 256>>>(X1, X2, p1, p2);
    Cvt9 cv;
    cv.g[0] = { W_pool1, OW_POOL1, 1048576L };
    cv.g[1] = { W_pool2, OW_POOL2, 1048576L };
    cv.g[2] = { W_loc1,  OW_LOC1,  1048576L };   // rows 0..1023 only
    cv.g[3] = { W_loc2,  OW_LOC2,  1048576L };   // rows 0..1023 only
    cv.g[4] = { W_os,    OW_OS,    2097152L };
    cv.g[5] = { W_ss,    OW_SS,    4194304L };
    cv.g[6] = { W_h1,    OW_H1,    6291456L };   // full 3072x2048
    cv.g[7] = { W_h2,    OW_H2,    4194304L };
    cv.g[8] = { W_q,     OW_Q,     3072000L };   // full 3072x1000
    cvt_kernel<<<dim3(2048, 9), 256>>>(cv, wh, wl);

    // ---- setup GEMMs ----
    launch_mgemm(p1, 1024, nullptr, 0, wh + OW_POOL1, wl + OW_POOL1, nullptr, nullptr, 1024,
                 b_pool1, nullptr, 0, tA, 1024, 1024, ACT_TANH, 16, part, cnt);
    launch_mgemm(p2, 1024, nullptr, 0, wh + OW_POOL2, wl + OW_POOL2, nullptr, nullptr, 1024,
                 b_pool2, nullptr, 0, tB, 1024, 1024, ACT_TANH, 16, part, cnt);
    launch_mgemm(p1, 1024, nullptr, 0, wh + OW_LOC1, wl + OW_LOC1, nullptr, nullptr, 1024,
                 b_loc1, nullptr, 0, bvis, 1024, 1024, ACT_NONE, 16, part, cnt);
    launch_mgemm(p2, 1024, nullptr, 0, wh + OW_LOC2, wl + OW_LOC2, nullptr, nullptr, 1024,
                 b_loc2, nullptr, 0, baud, 1024, 1024, ACT_NONE, 16, part, cnt);
    combine_kernel<<<256, 256>>>(tA, tB, o0);
    // s1 = tanh(o0 @ W_os + b_s)     (s0 = 0, W_ss term vanishes)
    launch_mgemm(o0, 1024, nullptr, 0, wh + OW_OS, wl + OW_OS, nullptr, nullptr, 2048,
                 b_s, nullptr, 0, sA, 2048, 2048, ACT_TANH, 16, part, cnt);
    // c_z = z @ W_h1[z-part] + b_h1   (loop-invariant)
    launch_mgemm(z, 1024, nullptr, 0, wh + OW_H1 + 2048L * 2048, wl + OW_H1 + 2048L * 2048,
                 nullptr, nullptr, 2048, b_h1, nullptr, 0, cz, 2048, 2048, ACT_NONE, 16, part, cnt);
    // c_q = z @ W_q[z-part] + b_q     (loop-invariant)
    launch_mgemm(z, 1024, nullptr, 0, wh + OW_Q + 2048L * 1000, wl + OW_Q + 2048L * 1000,
                 nullptr, nullptr, 1000, b_q, nullptr, 0, cq, 1000, 1000, ACT_NONE, 16, part, cnt);

    float* scur = sA;
    float* snxt = sB;

    // ---- T = 4 sequential steps ----
    for (int t = 0; t < 4; t++) {
        // h1 = relu(s @ W_h1[s-part] + c_z)
        launch_mgemm(scur, 2048, nullptr, 0, wh + OW_H1, wl + OW_H1, nullptr, nullptr, 2048,
                     nullptr, cz, 2048, h1, 2048, 2048, ACT_RELU, 16, part, cnt);
        // h2 = relu(h1 @ W_h2 + b_h2)
        launch_mgemm(h1, 2048, nullptr, 0, wh + OW_H2, wl + OW_H2, nullptr, nullptr, 2048,
                     b_h2, nullptr, 0, h2, 2048, 2048, ACT_RELU, 16, part, cnt);
        // policy: argmax + location + routed o_t
        policy_kernel<<<64, 256>>>(h2, W_M, b_M, W_L, b_L, W_loc1, W_loc2, bvis, baud, ot);
        // s' = tanh(s @ W_ss + o_t @ W_os + b_s)
        launch_mgemm(scur, 2048, ot, 1024, wh + OW_SS, wl + OW_SS, wh + OW_OS, wl + OW_OS, 2048,
                     b_s, nullptr, 0, snxt, 2048, 2048, ACT_TANH, 16, part, cnt);
        // y_t = s' @ W_q[s-part] + c_q
        launch_mgemm(snxt, 2048, nullptr, 0, wh + OW_Q, wl + OW_Q, nullptr, nullptr, 1000,
                     nullptr, cq, 1000, out + t * 1000, 4000, 1000, ACT_NONE, 32, part, cnt);
        float* tmp = scur; scur = snxt; snxt = tmp;
    }
}

// round 17
// speedup vs baseline: 1.4845x; 1.0878x over previous
#include <cuda_runtime.h>
#include <cuda_bf16.h>
#include <math.h>

typedef __nv_bfloat16 bf16;

#define ACT_NONE 0
#define ACT_TANH 1
#define ACT_RELU 2

// ---------------- fp32 scratch ----------------
#define OF_P1   0
#define OF_P2   65536
#define OF_TA   131072
#define OF_TB   196608
#define OF_O0   262144
#define OF_BV   327680
#define OF_BA   393216
#define OF_CZ   458752
#define OF_CQ   589824
#define OF_S0   655360
#define OF_S1   786432
#define OF_H1   917504
#define OF_H2   1048576
#define OF_OT   1179648
#define OF_PART 1245184
#define OF_CNT  3342336
#define F_TOTAL 3342464
__device__ float g_f[F_TOTAL];

// ---------------- bf16 hi/lo weight scratch ----------------
#define OW_POOL1 0L
#define OW_POOL2 1048576L
#define OW_LOC1  2097152L
#define OW_LOC2  3145728L
#define OW_OS    4194304L
#define OW_SS    6291456L
#define OW_H1    10485760L
#define OW_H2    16777216L
#define OW_Q     20971520L
#define W_TOTAL  24043520L
__device__ bf16 g_h[W_TOTAL];
__device__ bf16 g_l[W_TOTAL];

// ---------------- small helpers ----------------
__device__ __forceinline__ unsigned smem_u32(const void* p) {
    return (unsigned)__cvta_generic_to_shared(p);
}
__device__ __forceinline__ void cp16(unsigned dst, const void* src) {
    asm volatile("cp.async.cg.shared.global [%0], [%1], 16;\n" :: "r"(dst), "l"(src));
}
__device__ __forceinline__ void cp_commit() { asm volatile("cp.async.commit_group;\n"); }
__device__ __forceinline__ void cp_wait0()  { asm volatile("cp.async.wait_group 0;\n"); }

__device__ __forceinline__ void ldsm4(unsigned r[4], unsigned addr) {
    asm volatile("ldmatrix.sync.aligned.m8n8.x4.shared.b16 {%0,%1,%2,%3},[%4];\n"
                 : "=r"(r[0]), "=r"(r[1]), "=r"(r[2]), "=r"(r[3]) : "r"(addr));
}
__device__ __forceinline__ void ldsm4t(unsigned r[4], unsigned addr) {
    asm volatile("ldmatrix.sync.aligned.m8n8.x4.trans.shared.b16 {%0,%1,%2,%3},[%4];\n"
                 : "=r"(r[0]), "=r"(r[1]), "=r"(r[2]), "=r"(r[3]) : "r"(addr));
}
__device__ __forceinline__ void mma_bf16(float c[4], const unsigned a[4], unsigned b0, unsigned b1) {
    asm volatile(
        "mma.sync.aligned.m16n8k16.row.col.f32.bf16.bf16.f32 "
        "{%0,%1,%2,%3},{%4,%5,%6,%7},{%8,%9},{%0,%1,%2,%3};\n"
        : "+f"(c[0]), "+f"(c[1]), "+f"(c[2]), "+f"(c[3])
        : "r"(a[0]), "r"(a[1]), "r"(a[2]), "r"(a[3]), "r"(b0), "r"(b1));
}
__device__ __forceinline__ unsigned pk(bf16 a, bf16 b) {
    unsigned short ua = *(unsigned short*)&a, ub = *(unsigned short*)&b;
    return (unsigned)ua | ((unsigned)ub << 16);
}

// ============================================================================
// Pooling: mean over token axis. X1 (64,196,1024), X2 (64,400,1024)
// ============================================================================
__global__ void __launch_bounds__(256) pool_kernel(
    const float* __restrict__ X1, const float* __restrict__ X2,
    float* __restrict__ p1, float* __restrict__ p2)
{
    int b = blockIdx.x, y = blockIdx.y;
    int d = (y & 3) * 256 + threadIdx.x;
    if (y < 4) {
        const float* p = X1 + ((size_t)b * 196) * 1024 + d;
        float a = 0.f;
        #pragma unroll 4
        for (int n = 0; n < 196; n++) a += p[(size_t)n * 1024];
        p1[b * 1024 + d] = a * (1.0f / 196.0f);
    } else {
        const float* p = X2 + ((size_t)b * 400) * 1024 + d;
        float a = 0.f;
        #pragma unroll 4
        for (int n = 0; n < 400; n++) a += p[(size_t)n * 1024];
        p2[b * 1024 + d] = a * (1.0f / 400.0f);
    }
}

// ============================================================================
// Weight conversion: fp32 -> (hi, lo) bf16 pairs.  9 segments in one launch.
// ============================================================================
struct Seg  { const float* s; long off; long n; };
struct Cvt9 { Seg g[9]; };

__global__ void __launch_bounds__(256) cvt_kernel(Cvt9 a, bf16* __restrict__ H, bf16* __restrict__ L)
{
    Seg sg = a.g[blockIdx.y];
    long stride = (long)gridDim.x * 256 * 4;
    for (long i = ((long)blockIdx.x * 256 + threadIdx.x) * 4; i < sg.n; i += stride) {
        float4 v = *(const float4*)(sg.s + i);
        bf16 h0 = __float2bfloat16(v.x), h1 = __float2bfloat16(v.y);
        bf16 h2 = __float2bfloat16(v.z), h3 = __float2bfloat16(v.w);
        bf16 l0 = __float2bfloat16(v.x - __bfloat162float(h0));
        bf16 l1 = __float2bfloat16(v.y - __bfloat162float(h1));
        bf16 l2 = __float2bfloat16(v.z - __bfloat162float(h2));
        bf16 l3 = __float2bfloat16(v.w - __bfloat162float(h3));
        uint2 uh = make_uint2(pk(h0, h1), pk(h2, h3));
        uint2 ul = make_uint2(pk(l0, l1), pk(l2, l3));
        *(uint2*)(H + sg.off + i) = uh;
        *(uint2*)(L + sg.off + i) = ul;
    }
}

// ============================================================================
// o0 = 0.5 * (tA + tB)
// ============================================================================
__global__ void __launch_bounds__(256) combine_kernel(
    const float* __restrict__ a, const float* __restrict__ b, float* __restrict__ o)
{
    int i = blockIdx.x * 256 + threadIdx.x;
    o[i] = 0.5f * (a[i] + b[i]);
}

// ============================================================================
// Split-bf16 tensor-core GEMM, M=64 (SK = compile-time split-K factor):
//   C = act( [A0|A1] @ [W0;W1] + bias + Dadd )
// computed as a_hi*w_hi + a_hi*w_lo + a_lo*w_hi with fp32 accumulation.
// Last block per column tile (atomic counter) reduces partials with a FULLY
// UNROLLED sp-loop (compile-time SK) so all SK loads per position are in
// flight concurrently (previous runtime-SK loop serialized 256 L2 loads and
// dominated the kernel at ~35us).
// Tile: BM=64, BN=128, BK=32(fp32 K), 256 thr (8 warps, 2x4, warp tile 32x32).
// ============================================================================
template <int SK>
__global__ void __launch_bounds__(256) mgemm(
    const float* __restrict__ A0, int K0,
    const float* __restrict__ A1, int K1,
    const bf16* __restrict__ Wh0, const bf16* __restrict__ Wl0,
    const bf16* __restrict__ Wh1, const bf16* __restrict__ Wl1, int ldw,
    const float* __restrict__ bias, const float* __restrict__ Dadd, int ldd,
    float* __restrict__ partial, int pld,
    float* __restrict__ out, int ldo,
    int N, int act, int Kchunk, int* __restrict__ counters)
{
    __shared__ __align__(16) bf16 sAh[64 * 40];
    __shared__ __align__(16) bf16 sAl[64 * 40];
    __shared__ __align__(16) bf16 sW[2][2][32 * 136];   // [buf][hi/lo]

    const int tid = threadIdx.x;
    const int lane = tid & 31, warp = tid >> 5;
    const int wm = warp >> 2, wn = warp & 3;
    const int colblk = blockIdx.x, split = blockIdx.y;
    const int n0 = colblk * 128;

    float acc[2][4][4];
    #pragma unroll
    for (int i = 0; i < 2; i++)
        #pragma unroll
        for (int j = 0; j < 4; j++)
            #pragma unroll
            for (int r = 0; r < 4; r++) acc[i][j][r] = 0.f;

    // loader indices
    const int ar = tid >> 2;            // A row 0..63
    const int ac = (tid & 3) * 8;       // A k-offset 0,8,16,24
    const int wr = tid >> 3;            // W k-row 0..31
    const int wc = (tid & 7) * 16;      // W n-offset 0..112
    const int wn_g = n0 + wc;
    const bool wv0 = (wn_g     < N);
    const bool wv1 = (wn_g + 8 < N);

    // fragment smem byte offsets
    const unsigned aBaseH = smem_u32(sAh);
    const unsigned aBaseL = smem_u32(sAl);
    const unsigned aoff0 = (unsigned)(((wm * 32 + (lane & 15)) * 40 + (lane >> 4) * 8) * 2);
    const unsigned aoff1 = aoff0 + 16 * 40 * 2;
    const unsigned woff0 = (unsigned)((((lane & 7) + ((lane >> 3) & 1) * 8) * 136
                                      + wn * 32 + (lane >> 4) * 8) * 2);
    const unsigned woff1 = woff0 + 32;

    const int kbeg = split * Kchunk;
    const int nchunks = Kchunk / 32;

    float areg[8];

    auto loadA = [&](int kg) {
        bool p0 = (kg < K0);
        const float* Ap = p0 ? A0 : A1;
        int Kp = p0 ? K0 : K1;
        const float4* s = (const float4*)(Ap + (size_t)ar * Kp + (p0 ? kg : kg - K0) + ac);
        float4 u = s[0], v = s[1];
        areg[0] = u.x; areg[1] = u.y; areg[2] = u.z; areg[3] = u.w;
        areg[4] = v.x; areg[5] = v.y; areg[6] = v.z; areg[7] = v.w;
    };
    auto storeA = [&]() {
        bf16 h[8], l[8];
        #pragma unroll
        for (int j = 0; j < 8; j++) {
            h[j] = __float2bfloat16(areg[j]);
            l[j] = __float2bfloat16(areg[j] - __bfloat162float(h[j]));
        }
        *(uint4*)&sAh[ar * 40 + ac] = make_uint4(pk(h[0], h[1]), pk(h[2], h[3]), pk(h[4], h[5]), pk(h[6], h[7]));
        *(uint4*)&sAl[ar * 40 + ac] = make_uint4(pk(l[0], l[1]), pk(l[2], l[3]), pk(l[4], l[5]), pk(l[6], l[7]));
    };
    auto loadW = [&](int buf, int kg) {
        bool p0 = (kg < K0);
        const bf16* WH = p0 ? Wh0 : Wh1;
        const bf16* WL = p0 ? Wl0 : Wl1;
        size_t roff = (size_t)((p0 ? kg : kg - K0) + wr) * ldw + wn_g;
        bf16* dH = &sW[buf][0][wr * 136 + wc];
        bf16* dL = &sW[buf][1][wr * 136 + wc];
        if (wv0) { cp16(smem_u32(dH), WH + roff); cp16(smem_u32(dL), WL + roff); }
        else     { *(uint4*)dH = make_uint4(0,0,0,0); *(uint4*)dL = make_uint4(0,0,0,0); }
        if (wv1) { cp16(smem_u32(dH + 8), WH + roff + 8); cp16(smem_u32(dL + 8), WL + roff + 8); }
        else     { *(uint4*)(dH + 8) = make_uint4(0,0,0,0); *(uint4*)(dL + 8) = make_uint4(0,0,0,0); }
    };
    auto compute = [&](int buf) {
        #pragma unroll
        for (int p = 0; p < 3; p++) {
            unsigned aB = (p == 2) ? aBaseL : aBaseH;
            unsigned wB = smem_u32(&sW[buf][(p == 1) ? 1 : 0][0]);
            #pragma unroll
            for (int kk = 0; kk < 2; kk++) {
                unsigned a0[4], a1[4], b0r[4], b1r[4];
                ldsm4 (a0,  aB + aoff0 + kk * 32);
                ldsm4 (a1,  aB + aoff1 + kk * 32);
                ldsm4t(b0r, wB + woff0 + kk * 4352);
                ldsm4t(b1r, wB + woff1 + kk * 4352);
                mma_bf16(acc[0][0], a0, b0r[0], b0r[1]);
                mma_bf16(acc[0][1], a0, b0r[2], b0r[3]);
                mma_bf16(acc[0][2], a0, b1r[0], b1r[1]);
                mma_bf16(acc[0][3], a0, b1r[2], b1r[3]);
                mma_bf16(acc[1][0], a1, b0r[0], b0r[1]);
                mma_bf16(acc[1][1], a1, b0r[2], b0r[3]);
                mma_bf16(acc[1][2], a1, b1r[0], b1r[1]);
                mma_bf16(acc[1][3], a1, b1r[2], b1r[3]);
            }
        }
    };

    // prologue
    loadW(0, kbeg); cp_commit();
    loadA(kbeg); storeA();
    cp_wait0(); __syncthreads();

    for (int ci = 0; ci < nchunks; ci++) {
        int buf = ci & 1;
        bool nx = (ci + 1 < nchunks);
        if (nx) { loadW(buf ^ 1, kbeg + (ci + 1) * 32); cp_commit(); loadA(kbeg + (ci + 1) * 32); }
        compute(buf);
        __syncthreads();
        if (nx) storeA();
        cp_wait0();
        __syncthreads();
    }

    // ---- write split-K partials ----
    const int r0 = wm * 32 + (lane >> 2);
    const int c0 = wn * 32 + (lane & 3) * 2;
    #pragma unroll
    for (int mt = 0; mt < 2; mt++)
        #pragma unroll
        for (int nt = 0; nt < 4; nt++)
            #pragma unroll
            for (int pr = 0; pr < 2; pr++) {
                int row = r0 + mt * 16 + pr * 8;
                int col = n0 + c0 + nt * 8;
                *(float2*)&partial[((size_t)(split * 64 + row)) * pld + col] =
                    make_float2(acc[mt][nt][pr * 2], acc[mt][nt][pr * 2 + 1]);
            }

    __threadfence();
    __syncthreads();
    __shared__ int sLast;
    if (tid == 0) {
        int old = atomicAdd(&counters[colblk], 1);
        sLast = (old == SK - 1);
    }
    __syncthreads();
    if (!sLast) return;

    // last block: reduce with FULLY UNROLLED sp loop (SK is compile-time) so
    // all SK loads per position issue concurrently instead of a serial chain.
    #pragma unroll
    for (int mt = 0; mt < 2; mt++)
        #pragma unroll
        for (int nt = 0; nt < 4; nt++)
            #pragma unroll
            for (int pr = 0; pr < 2; pr++) {
                int row = r0 + mt * 16 + pr * 8;
                int col = n0 + c0 + nt * 8;
                if (col >= N) continue;
                float2 t[SK];
                #pragma unroll
                for (int sp = 0; sp < SK; sp++)
                    t[sp] = *(const float2*)&partial[((size_t)(sp * 64 + row)) * pld + col];
                float vx = 0.f, vy = 0.f;
                #pragma unroll
                for (int sp = 0; sp < SK; sp++) { vx += t[sp].x; vy += t[sp].y; }
                if (bias) { vx += bias[col]; vy += bias[col + 1]; }
                if (Dadd) { vx += Dadd[(size_t)row * ldd + col]; vy += Dadd[(size_t)row * ldd + col + 1]; }
                if (act == ACT_TANH) { vx = tanhf(vx); vy = tanhf(vy); }
                else if (act == ACT_RELU) { vx = fmaxf(vx, 0.f); vy = fmaxf(vy, 0.f); }
                out[(size_t)row * ldo + col]     = vx;
                out[(size_t)row * ldo + col + 1] = vy;
            }
    if (tid == 0) counters[colblk] = 0;
}

// ============================================================================
// Policy head: reads full h2 (already relu'd).  One block per sample:
//   logits = h2@W_M+b_M -> argmax; l = tanh(h2@W_L+b_L);
//   o_t = routed tanh(base + rank-1/2 update from l).
// ============================================================================
__global__ void __launch_bounds__(256) policy_kernel(
    const float* __restrict__ h2,
    const float* __restrict__ W_M, const float* __restrict__ b_M,
    const float* __restrict__ W_L, const float* __restrict__ b_L,
    const float* __restrict__ W_loc1, const float* __restrict__ W_loc2,
    const float* __restrict__ bvis, const float* __restrict__ baud,
    float* __restrict__ ot)
{
    int b = blockIdx.x, tid = threadIdx.x;
    float m0 = 0.f, m1 = 0.f, l0 = 0.f, l1 = 0.f;
    for (int k = tid; k < 2048; k += 256) {
        float v = h2[b * 2048 + k];
        m0 += v * W_M[2 * k];  m1 += v * W_M[2 * k + 1];
        l0 += v * W_L[2 * k];  l1 += v * W_L[2 * k + 1];
    }
    __shared__ float red[4][256];
    red[0][tid] = m0; red[1][tid] = m1; red[2][tid] = l0; red[3][tid] = l1;
    __syncthreads();
    for (int off = 128; off > 0; off >>= 1) {
        if (tid < off)
            #pragma unroll
            for (int c = 0; c < 4; c++) red[c][tid] += red[c][tid + off];
        __syncthreads();
    }
    __shared__ int s_m; __shared__ float s_l0, s_l1;
    if (tid == 0) {
        float q0 = red[0][0] + b_M[0], q1 = red[1][0] + b_M[1];
        s_m  = (q1 > q0) ? 1 : 0;
        s_l0 = tanhf(red[2][0] + b_L[0]);
        s_l1 = tanhf(red[3][0] + b_L[1]);
    }
    __syncthreads();
    int m = s_m; float L0 = s_l0, L1 = s_l1;
    const float* wl1a = W_loc1 + (size_t)1024 * 1024;
    const float* wl1b = W_loc1 + (size_t)1025 * 1024;
    const float* wl2a = W_loc2 + (size_t)1024 * 1024;
    for (int d = tid; d < 1024; d += 256) {
        float o;
        if (m == 0) o = tanhf(bvis[b * 1024 + d] + L0 * wl1a[d] + L1 * wl1b[d]);
        else        o = tanhf(baud[b * 1024 + d] + L0 * wl2a[d]);
        ot[b * 1024 + d] = o;
    }
}

// ============================================================================
// Host driver
// ============================================================================
static inline void launch_mgemm(const float* A0, int K0, const float* A1, int K1,
                                const bf16* Wh0, const bf16* Wl0,
                                const bf16* Wh1, const bf16* Wl1, int ldw,
                                const float* bias, const float* Dadd, int ldd,
                                float* out, int ldo, int N, int act, int SK,
                                float* part, int* cnt)
{
    int cb = (N + 127) / 128;
    int Kchunk = (K0 + K1) / SK;
    dim3 grid(cb, SK);
    switch (SK) {
    case 8:
        mgemm<8><<<grid, 256>>>(A0, K0, A1, K1, Wh0, Wl0, Wh1, Wl1, ldw, bias, Dadd, ldd,
                                part, cb * 128, out, ldo, N, act, Kchunk, cnt);
        break;
    case 16:
        mgemm<16><<<grid, 256>>>(A0, K0, A1, K1, Wh0, Wl0, Wh1, Wl1, ldw, bias, Dadd, ldd,
                                 part, cb * 128, out, ldo, N, act, Kchunk, cnt);
        break;
    case 32:
        mgemm<32><<<grid, 256>>>(A0, K0, A1, K1, Wh0, Wl0, Wh1, Wl1, ldw, bias, Dadd, ldd,
                                 part, cb * 128, out, ldo, N, act, Kchunk, cnt);
        break;
    default:
        mgemm<4><<<grid, 256>>>(A0, K0, A1, K1, Wh0, Wl0, Wh1, Wl1, ldw, bias, Dadd, ldd,
                                part, cb * 128, out, ldo, N, act, Kchunk, cnt);
        break;
    }
}

extern "C" void kernel_launch(void* const* d_in, const int* in_sizes, int n_in,
                              void* d_out, int out_size)
{
    const float* X1      = (const float*)d_in[0];
    const float* X2      = (const float*)d_in[1];
    const float* z       = (const float*)d_in[2];
    const float* W_pool1 = (const float*)d_in[3];
    const float* b_pool1 = (const float*)d_in[4];
    const float* W_loc1  = (const float*)d_in[5];
    const float* b_loc1  = (const float*)d_in[6];
    const float* W_pool2 = (const float*)d_in[7];
    const float* b_pool2 = (const float*)d_in[8];
    const float* W_loc2  = (const float*)d_in[9];
    const float* b_loc2  = (const float*)d_in[10];
    const float* W_ss    = (const float*)d_in[11];
    const float* W_os    = (const float*)d_in[12];
    const float* b_s     = (const float*)d_in[13];
    const float* W_h1    = (const float*)d_in[14];
    const float* b_h1    = (const float*)d_in[15];
    const float* W_h2    = (const float*)d_in[16];
    const float* b_h2    = (const float*)d_in[17];
    const float* W_M     = (const float*)d_in[18];
    const float* b_M     = (const float*)d_in[19];
    const float* W_L     = (const float*)d_in[20];
    const float* b_L     = (const float*)d_in[21];
    const float* W_q     = (const float*)d_in[24];
    const float* b_q     = (const float*)d_in[25];
    float* out = (float*)d_out;

    float* fb = nullptr;  bf16* wh = nullptr;  bf16* wl = nullptr;
    cudaGetSymbolAddress((void**)&fb, g_f);
    cudaGetSymbolAddress((void**)&wh, g_h);
    cudaGetSymbolAddress((void**)&wl, g_l);

    float* p1   = fb + OF_P1;
    float* p2   = fb + OF_P2;
    float* tA   = fb + OF_TA;
    float* tB   = fb + OF_TB;
    float* o0   = fb + OF_O0;
    float* bvis = fb + OF_BV;
    float* baud = fb + OF_BA;
    float* cz   = fb + OF_CZ;
    float* cq   = fb + OF_CQ;
    float* sA   = fb + OF_S0;
    float* sB   = fb + OF_S1;
    float* h1   = fb + OF_H1;
    float* h2   = fb + OF_H2;
    float* ot   = fb + OF_OT;
    float* part = fb + OF_PART;
    int*   cnt  = (int*)(fb + OF_CNT);

    // ---- pooling + weight conversion ----
    pool_kernel<<<dim3(64, 8), 256>>>(X1, X2, p1, p2);
    Cvt9 cv;
    cv.g[0] = { W_pool1, OW_POOL1, 1048576L };
    cv.g[1] = { W_pool2, OW_POOL2, 1048576L };
    cv.g[2] = { W_loc1,  OW_LOC1,  1048576L };   // rows 0..1023 only
    cv.g[3] = { W_loc2,  OW_LOC2,  1048576L };   // rows 0..1023 only
    cv.g[4] = { W_os,    OW_OS,    2097152L };
    cv.g[5] = { W_ss,    OW_SS,    4194304L };
    cv.g[6] = { W_h1,    OW_H1,    6291456L };   // full 3072x2048
    cv.g[7] = { W_h2,    OW_H2,    4194304L };
    cv.g[8] = { W_q,     OW_Q,     3072000L };   // full 3072x1000
    cvt_kernel<<<dim3(2048, 9), 256>>>(cv, wh, wl);

    // ---- setup GEMMs ----
    launch_mgemm(p1, 1024, nullptr, 0, wh + OW_POOL1, wl + OW_POOL1, nullptr, nullptr, 1024,
                 b_pool1, nullptr, 0, tA, 1024, 1024, ACT_TANH, 16, part, cnt);
    launch_mgemm(p2, 1024, nullptr, 0, wh + OW_POOL2, wl + OW_POOL2, nullptr, nullptr, 1024,
                 b_pool2, nullptr, 0, tB, 1024, 1024, ACT_TANH, 16, part, cnt);
    launch_mgemm(p1, 1024, nullptr, 0, wh + OW_LOC1, wl + OW_LOC1, nullptr, nullptr, 1024,
                 b_loc1, nullptr, 0, bvis, 1024, 1024, ACT_NONE, 16, part, cnt);
    launch_mgemm(p2, 1024, nullptr, 0, wh + OW_LOC2, wl + OW_LOC2, nullptr, nullptr, 1024,
                 b_loc2, nullptr, 0, baud, 1024, 1024, ACT_NONE, 16, part, cnt);
    combine_kernel<<<256, 256>>>(tA, tB, o0);
    // s1 = tanh(o0 @ W_os + b_s)     (s0 = 0, W_ss term vanishes)
    launch_mgemm(o0, 1024, nullptr, 0, wh + OW_OS, wl + OW_OS, nullptr, nullptr, 2048,
                 b_s, nullptr, 0, sA, 2048, 2048, ACT_TANH, 16, part, cnt);
    // c_z = z @ W_h1[z-part] + b_h1   (loop-invariant)
    launch_mgemm(z, 1024, nullptr, 0, wh + OW_H1 + 2048L * 2048, wl + OW_H1 + 2048L * 2048,
                 nullptr, nullptr, 2048, b_h1, nullptr, 0, cz, 2048, 2048, ACT_NONE, 16, part, cnt);
    // c_q = z @ W_q[z-part] + b_q     (loop-invariant)
    launch_mgemm(z, 1024, nullptr, 0, wh + OW_Q + 2048L * 1000, wl + OW_Q + 2048L * 1000,
                 nullptr, nullptr, 1000, b_q, nullptr, 0, cq, 1000, 1000, ACT_NONE, 16, part, cnt);

    float* scur = sA;
    float* snxt = sB;

    // ---- T = 4 sequential steps ----
    for (int t = 0; t < 4; t++) {
        // h1 = relu(s @ W_h1[s-part] + c_z)
        launch_mgemm(scur, 2048, nullptr, 0, wh + OW_H1, wl + OW_H1, nullptr, nullptr, 2048,
                     nullptr, cz, 2048, h1, 2048, 2048, ACT_RELU, 16, part, cnt);
        // h2 = relu(h1 @ W_h2 + b_h2)
        launch_mgemm(h1, 2048, nullptr, 0, wh + OW_H2, wl + OW_H2, nullptr, nullptr, 2048,
                     b_h2, nullptr, 0, h2, 2048, 2048, ACT_RELU, 16, part, cnt);
        // policy: argmax + location + routed o_t
        policy_kernel<<<64, 256>>>(h2, W_M, b_M, W_L, b_L, W_loc1, W_loc2, bvis, baud, ot);
        // s' = tanh(s @ W_ss + o_t @ W_os + b_s)
        launch_mgemm(scur, 2048, ot, 1024, wh + OW_SS, wl + OW_SS, wh + OW_OS, wl + OW_OS, 2048,
                     b_s, nullptr, 0, snxt, 2048, 2048, ACT_TANH, 16, part, cnt);
        // y_t = s' @ W_q[s-part] + c_q
        launch_mgemm(snxt, 2048, nullptr, 0, wh + OW_Q, wl + OW_Q, nullptr, nullptr, 1000,
                     nullptr, cq, 1000, out + t * 1000, 4000, 1000, ACT_NONE, 32, part, cnt);
        float* tmp = scur; scur = snxt; snxt = tmp;
    }
}